// round 3
// baseline (speedup 1.0000x reference)
#include <cuda_runtime.h>

#define BB   8
#define NN   1024
#define FIN  25
#define HH   8
#define DD   16
#define TR   64         // rows per block (gemm)
#define CJ   64         // j per chunk
#define NJP  (CJ/2)     // 32 j-pairs per chunk

// smem word strides (floats)
#define QP_STRIDE 258   // per jjp: 128 ull (cols) + 1 pad  = 258 words
#define MP_STRIDE 132   // per jjp: 64 ull (rows) + 2 pad   = 132 words

// -------- device scratch --------
__device__ float g_Wh[(size_t)BB*HH*NN*DD];     // (b,h,n,d)
__device__ float g_ej[(size_t)BB*HH*NN];
__device__ float g_p [(size_t)BB*HH*NN];        // (b,h,n)
__device__ float g_Q [(size_t)BB*NN*128];       // (b,n,h*16+d)

__device__ __forceinline__ void fma2(unsigned long long& d,
                                     unsigned long long a, unsigned long long b) {
    asm("fma.rn.f32x2 %0, %1, %2, %0;" : "+l"(d) : "l"(a), "l"(b));
}
__device__ __forceinline__ void unpack2(unsigned long long v, float& lo, float& hi) {
    asm("mov.b64 {%0, %1}, %2;" : "=f"(lo), "=f"(hi) : "l"(v));
}
__device__ __forceinline__ unsigned long long pack2(float lo, float hi) {
    unsigned long long r;
    asm("mov.b64 %0, {%1, %2};" : "=l"(r) : "f"(lo), "f"(hi));
    return r;
}

// ============================================================
// Kernel 1: Wh = x@W per head, ej = Wh . a_dst
// ============================================================
__global__ __launch_bounds__(256) void gat_prep(const float* __restrict__ x,
                                                const float* __restrict__ W,
                                                const float* __restrict__ a) {
    __shared__ float s_W[HH * 401];
    __shared__ float s_x[32 * FIN];
    __shared__ float s_a[HH * 32];

    int tid = threadIdx.x;
    int b  = blockIdx.x >> 5;
    int n0 = (blockIdx.x & 31) * 32;

    for (int idx = tid; idx < HH * 400; idx += 256) {
        int h = idx / 400, rem = idx - h * 400;
        s_W[h * 401 + rem] = W[idx];
    }
    s_a[tid] = a[tid];
    for (int idx = tid; idx < 32 * FIN; idx += 256)
        s_x[idx] = x[((size_t)b * NN + n0) * FIN + idx];
    __syncthreads();

    int nl = tid >> 3;
    int h  = tid & 7;

    float wh[DD];
    #pragma unroll
    for (int d = 0; d < DD; d++) wh[d] = 0.f;

    const float* wbase = &s_W[h * 401];
    const float* xr    = &s_x[nl * FIN];
    #pragma unroll
    for (int f = 0; f < FIN; f++) {
        float xv = xr[f];
        #pragma unroll
        for (int d = 0; d < DD; d++) wh[d] += xv * wbase[f * 16 + d];
    }

    float e2 = 0.f;
    #pragma unroll
    for (int d = 0; d < DD; d++) e2 += wh[d] * s_a[h * 32 + 16 + d];

    size_t base = ((size_t)(b * HH + h) * NN + n0 + nl);
    float4* dst = (float4*)&g_Wh[base * DD];
    dst[0] = make_float4(wh[0],  wh[1],  wh[2],  wh[3]);
    dst[1] = make_float4(wh[4],  wh[5],  wh[6],  wh[7]);
    dst[2] = make_float4(wh[8],  wh[9],  wh[10], wh[11]);
    dst[3] = make_float4(wh[12], wh[13], wh[14], wh[15]);
    g_ej[base] = e2;
}

// ============================================================
// Kernel 2: per (b,h): M = max_j ej, p = exp(ej-M), Q = p*Wh
// ============================================================
__global__ __launch_bounds__(256) void gat_pexp() {
    __shared__ float wmax[8];
    int tid = threadIdx.x, lane = tid & 31, warp = tid >> 5;
    int bh = blockIdx.x, b = bh >> 3, h = bh & 7;

    float4 e = ((const float4*)(g_ej + (size_t)bh * NN))[tid];
    float m = fmaxf(fmaxf(e.x, e.y), fmaxf(e.z, e.w));
    #pragma unroll
    for (int off = 16; off; off >>= 1)
        m = fmaxf(m, __shfl_xor_sync(0xffffffffu, m, off));
    if (lane == 0) wmax[warp] = m;
    __syncthreads();
    float M = wmax[0];
    #pragma unroll
    for (int w = 1; w < 8; w++) M = fmaxf(M, wmax[w]);

    float4 p = make_float4(__expf(e.x - M), __expf(e.y - M),
                           __expf(e.z - M), __expf(e.w - M));
    ((float4*)(g_p + (size_t)bh * NN))[tid] = p;

    const float pv[4] = {p.x, p.y, p.z, p.w};
    #pragma unroll
    for (int k = 0; k < 4; k++) {
        int j = tid * 4 + k;
        const float4* wsrc = (const float4*)&g_Wh[((size_t)bh * NN + j) * DD];
        float4* qdst = (float4*)&g_Q[((size_t)b * NN + j) * 128 + h * DD];
        float pk = pv[k];
        #pragma unroll
        for (int q = 0; q < 4; q++) {
            float4 w = wsrc[q];
            qdst[q] = make_float4(w.x * pk, w.y * pk, w.z * pk, w.w * pk);
        }
    }
}

// ============================================================
// Kernel 3 (fused): per block = (b, 64-row tile)
//   pre-pass:  S[i][h] -> invS in smem
//   chunk loop (64 j):
//     stage Q pair-packed transposed, masks pair-packed
//     FFMA2 K-packed GEMM accumulation (FMA-pipe bound)
//     stream alpha chunk to gmem (overlaps DRAM with FMA of later chunks)
//   epilogue: hprime = relu(H * invS)
// grid 128, 256 threads
// ============================================================
extern __shared__ char dynsmem[];

__global__ __launch_bounds__(256) void gat_fused(const int* __restrict__ adj,
                                                 float* __restrict__ hprime,
                                                 float* __restrict__ alpha) {
    float* sQp = (float*)dynsmem;               // [NJP][QP_STRIDE] 33KB
    float* sMp = sQp + NJP * QP_STRIDE;         // [NJP][MP_STRIDE] 16.9KB
    float* sP  = sMp + NJP * MP_STRIDE;         // [8][1024] 32KB
    float* sS  = sP + 8 * NN;                   // [64][8] invS 2KB

    int tid = threadIdx.x;
    int warp = tid >> 5, lane = tid & 31;
    int c4 = tid & 31, rg = tid >> 5;           // cols c4+32k, rows rg*8..+7
    int b  = blockIdx.x >> 4;
    int i0 = (blockIdx.x & 15) * TR;

    // ---- stage p (whole batch, 8 heads) ----
    for (int k = tid; k < 2048; k += 256)
        ((float4*)sP)[k] = ((const float4*)(g_p + (size_t)b * HH * NN))[k];
    __syncthreads();

    // ---- S pre-pass: warp w -> rows w*8..w*8+7 ----
    for (int rr = 0; rr < 8; rr++) {
        int r = warp * 8 + rr;
        const int4* arow4 = (const int4*)(adj + ((size_t)b * NN + i0 + r) * NN);
        float s[8];
        #pragma unroll
        for (int h = 0; h < 8; h++) s[h] = 0.f;
        #pragma unroll 2
        for (int j4 = lane; j4 < 256; j4 += 32) {
            int4 av = arow4[j4];
            float m0 = (float)av.x, m1 = (float)av.y;
            float m2 = (float)av.z, m3 = (float)av.w;
            int j = j4 * 4;
            #pragma unroll
            for (int h = 0; h < 8; h++) {
                float4 pv = *(const float4*)&sP[h * NN + j];
                s[h] += m0 * pv.x + m1 * pv.y + m2 * pv.z + m3 * pv.w;
            }
        }
        #pragma unroll
        for (int h = 0; h < 8; h++) {
            float v = s[h];
            #pragma unroll
            for (int off = 16; off; off >>= 1)
                v += __shfl_xor_sync(0xffffffffu, v, off);
            s[h] = v;
        }
        if (lane < 8)
            sS[r * 8 + lane] = (s[lane] > 0.f) ? (1.f / s[lane]) : (1.f / NN);
    }
    __syncthreads();

    // ---- accumulators: rows rg*8+r (r 0..7), cols c4+32k (k 0..3), K-packed ----
    unsigned long long acc[8][4];
    #pragma unroll
    for (int r = 0; r < 8; r++)
        #pragma unroll
        for (int k = 0; k < 4; k++) acc[r][k] = 0ull;

    for (int jc = 0; jc < NN; jc += CJ) {
        __syncthreads();   // protect sQp/sMp reuse (and alpha-write reads of prev chunk)

        // -- stage Q: [jjp][c] pair-packed. lanes = consecutive jj --
        {
            int jj  = tid & 63;                 // 0..63
            int c4g0 = (tid >> 6) * 4;          // 0,4,8,12 base over k-iters
            const float4* gq = (const float4*)(g_Q + ((size_t)b * NN + jc) * 128);
            #pragma unroll
            for (int k = 0; k < 8; k++) {
                int c4g = c4g0 + (k & 3) + (k >> 2) * 16;   // covers 0..31
                float4 v = gq[jj * 32 + c4g];
                int base = (jj >> 1) * QP_STRIDE + (jj & 1);
                int c = c4g * 4;
                sQp[base + (c + 0) * 2] = v.x;
                sQp[base + (c + 1) * 2] = v.y;
                sQp[base + (c + 2) * 2] = v.z;
                sQp[base + (c + 3) * 2] = v.w;
            }
        }
        // -- stage masks: [jjp][row] pair-packed. lanes = consecutive rows --
        {
            int row  = tid & 63;
            int cc40 = tid >> 6;                // 0..3
            #pragma unroll
            for (int k = 0; k < 4; k++) {
                int cc4 = cc40 + k * 4;         // 0..15
                int4 av = *(const int4*)(adj + ((size_t)b * NN + i0 + row) * NN + jc + cc4 * 4);
                int jjp0 = cc4 * 2;
                *(unsigned long long*)&sMp[jjp0 * MP_STRIDE + row * 2] =
                    pack2((float)av.x, (float)av.y);
                *(unsigned long long*)&sMp[(jjp0 + 1) * MP_STRIDE + row * 2] =
                    pack2((float)av.z, (float)av.w);
            }
        }
        __syncthreads();

        // -- FMA inner loop --
        #pragma unroll 2
        for (int jjp = 0; jjp < NJP; jjp++) {
            const float* qb = &sQp[jjp * QP_STRIDE];
            unsigned long long q0 = *(const unsigned long long*)&qb[(c4 +  0) * 2];
            unsigned long long q1 = *(const unsigned long long*)&qb[(c4 + 32) * 2];
            unsigned long long q2 = *(const unsigned long long*)&qb[(c4 + 64) * 2];
            unsigned long long q3 = *(const unsigned long long*)&qb[(c4 + 96) * 2];
            const float* mb = &sMp[jjp * MP_STRIDE + rg * 16];
            ulonglong2 ma = *(const ulonglong2*)&mb[0];
            ulonglong2 mbv = *(const ulonglong2*)&mb[4];
            ulonglong2 mc = *(const ulonglong2*)&mb[8];
            ulonglong2 md = *(const ulonglong2*)&mb[12];
            fma2(acc[0][0], ma.x, q0);  fma2(acc[0][1], ma.x, q1);
            fma2(acc[0][2], ma.x, q2);  fma2(acc[0][3], ma.x, q3);
            fma2(acc[1][0], ma.y, q0);  fma2(acc[1][1], ma.y, q1);
            fma2(acc[1][2], ma.y, q2);  fma2(acc[1][3], ma.y, q3);
            fma2(acc[2][0], mbv.x, q0); fma2(acc[2][1], mbv.x, q1);
            fma2(acc[2][2], mbv.x, q2); fma2(acc[2][3], mbv.x, q3);
            fma2(acc[3][0], mbv.y, q0); fma2(acc[3][1], mbv.y, q1);
            fma2(acc[3][2], mbv.y, q2); fma2(acc[3][3], mbv.y, q3);
            fma2(acc[4][0], mc.x, q0);  fma2(acc[4][1], mc.x, q1);
            fma2(acc[4][2], mc.x, q2);  fma2(acc[4][3], mc.x, q3);
            fma2(acc[5][0], mc.y, q0);  fma2(acc[5][1], mc.y, q1);
            fma2(acc[5][2], mc.y, q2);  fma2(acc[5][3], mc.y, q3);
            fma2(acc[6][0], md.x, q0);  fma2(acc[6][1], md.x, q1);
            fma2(acc[6][2], md.x, q2);  fma2(acc[6][3], md.x, q3);
            fma2(acc[7][0], md.y, q0);  fma2(acc[7][1], md.y, q1);
            fma2(acc[7][2], md.y, q2);  fma2(acc[7][3], md.y, q3);
        }

        // -- stream alpha chunk: warp = head, halves of warp = row pairs --
        {
            int h = warp;
            int jj4 = lane & 15;
            int j = jc + jj4 * 4;
            float4 p4 = *(const float4*)&sP[h * NN + j];
            size_t abase = (((size_t)(b * HH + h)) * NN + i0) * NN;
            #pragma unroll 2
            for (int it = 0; it < 32; it++) {
                int row = it * 2 + (lane >> 4);
                int4 av = *(const int4*)(adj + ((size_t)b * NN + i0 + row) * NN + j);
                float inv = sS[row * 8 + h];
                float4 o = make_float4((float)av.x * (p4.x * inv),
                                       (float)av.y * (p4.y * inv),
                                       (float)av.z * (p4.z * inv),
                                       (float)av.w * (p4.w * inv));
                __stwt((float4*)&alpha[abase + (size_t)row * NN + j], o);
            }
        }
    }

    // ---- epilogue: hprime = relu((lo+hi) * invS) ----
    #pragma unroll
    for (int r = 0; r < 8; r++) {
        int row = rg * 8 + r;
        float* orow = hprime + ((size_t)b * NN + i0 + row) * 128;
        #pragma unroll
        for (int k = 0; k < 4; k++) {
            int c = c4 + 32 * k;
            float lo, hi;
            unpack2(acc[r][k], lo, hi);
            float inv = sS[row * 8 + (c >> 4)];
            orow[c] = fmaxf((lo + hi) * inv, 0.f);
        }
    }
}

// ============================================================
extern "C" void kernel_launch(void* const* d_in, const int* in_sizes, int n_in,
                              void* d_out, int out_size) {
    const float* x   = (const float*)d_in[0];   // (8,1024,25)
    const int*   adj = (const int*)  d_in[1];   // (8,1024,1024)
    const float* W   = (const float*)d_in[2];   // (8,25,16)
    const float* a   = (const float*)d_in[3];   // (8,32,1)

    float* out    = (float*)d_out;
    float* hprime = out;                                 // (8,1024,128)
    float* alpha  = out + (size_t)BB * NN * HH * DD;     // (8,8,1024,1024)

    const int fused_smem = (NJP * QP_STRIDE + NJP * MP_STRIDE + 8 * NN + TR * 8) * 4;
    cudaFuncSetAttribute(gat_fused, cudaFuncAttributeMaxDynamicSharedMemorySize, fused_smem);

    gat_prep<<<BB * (NN / 32), 256>>>(x, W, a);
    gat_pexp<<<BB * HH, 256>>>();
    gat_fused<<<BB * (NN / TR), 256, fused_smem>>>(adj, hprime, alpha);
}

// round 10
// speedup vs baseline: 1.1997x; 1.1997x over previous
#include <cuda_runtime.h>
#include <cuda_bf16.h>
#include <cstdint>

#define BB 8
#define NN 1024
#define FIN 25
#define HH 8
#define DD 16

// -------- device scratch --------
__device__ float g_Wh[(size_t)BB*HH*NN*DD];         // (b,h,n,d) 4MB
__device__ float g_ej[(size_t)BB*HH*NN];
__device__ float g_p [(size_t)BB*HH*NN];            // (b,h,n)
__device__ float g_invS[(size_t)BB*NN*HH];          // (b,n,h)
__device__ unsigned short g_adjb[(size_t)BB*NN*NN]; // adj as bf16, 16MB
__device__ unsigned short g_Qth[(size_t)BB*128*NN]; // Q^T hi bf16 (b,c,j) 2MB
__device__ unsigned short g_Qtl[(size_t)BB*128*NN]; // Q^T lo bf16 2MB

// ---- helpers ----
__device__ __forceinline__ uint32_t smem_u32(const void* p) {
    uint32_t a;
    asm("{ .reg .u64 t; cvta.to.shared.u64 t, %1; cvt.u32.u64 %0, t; }" : "=r"(a) : "l"(p));
    return a;
}
__device__ __forceinline__ unsigned cvt2bf(float lo, float hi) {
    unsigned r;
    asm("cvt.rn.bf16x2.f32 %0, %1, %2;" : "=r"(r) : "f"(hi), "f"(lo));
    return r;
}
__device__ __forceinline__ void ldmx4(uint32_t& r0, uint32_t& r1, uint32_t& r2,
                                      uint32_t& r3, uint32_t addr) {
    asm volatile("ldmatrix.sync.aligned.m8n8.x4.shared.b16 {%0,%1,%2,%3}, [%4];"
                 : "=r"(r0), "=r"(r1), "=r"(r2), "=r"(r3) : "r"(addr));
}
__device__ __forceinline__ void mma16816(float* d, const uint32_t* a,
                                         uint32_t b0, uint32_t b1) {
    asm volatile("mma.sync.aligned.m16n8k16.row.col.f32.bf16.bf16.f32 "
                 "{%0,%1,%2,%3}, {%4,%5,%6,%7}, {%8,%9}, {%0,%1,%2,%3};"
                 : "+f"(d[0]), "+f"(d[1]), "+f"(d[2]), "+f"(d[3])
                 : "r"(a[0]), "r"(a[1]), "r"(a[2]), "r"(a[3]), "r"(b0), "r"(b1));
}

// ============================================================
// K1: Wh = x@W per head, ej = Wh . a_dst
// ============================================================
__global__ __launch_bounds__(256) void gat_prep(const float* __restrict__ x,
                                                const float* __restrict__ W,
                                                const float* __restrict__ a) {
    __shared__ float s_W[HH * 401];
    __shared__ float s_x[32 * FIN];
    __shared__ float s_a[HH * 32];

    int tid = threadIdx.x;
    int b  = blockIdx.x >> 5;
    int n0 = (blockIdx.x & 31) * 32;

    for (int idx = tid; idx < HH * 400; idx += 256) {
        int h = idx / 400, rem = idx - h * 400;
        s_W[h * 401 + rem] = W[idx];
    }
    s_a[tid] = a[tid];
    for (int idx = tid; idx < 32 * FIN; idx += 256)
        s_x[idx] = x[((size_t)b * NN + n0) * FIN + idx];
    __syncthreads();

    int nl = tid >> 3;
    int h  = tid & 7;

    float wh[DD];
    #pragma unroll
    for (int d = 0; d < DD; d++) wh[d] = 0.f;

    const float* wbase = &s_W[h * 401];
    const float* xr    = &s_x[nl * FIN];
    #pragma unroll
    for (int f = 0; f < FIN; f++) {
        float xv = xr[f];
        #pragma unroll
        for (int d = 0; d < DD; d++) wh[d] += xv * wbase[f * 16 + d];
    }

    float e2 = 0.f;
    #pragma unroll
    for (int d = 0; d < DD; d++) e2 += wh[d] * s_a[h * 32 + 16 + d];

    size_t base = ((size_t)(b * HH + h) * NN + n0 + nl);
    float4* dst = (float4*)&g_Wh[base * DD];
    dst[0] = make_float4(wh[0],  wh[1],  wh[2],  wh[3]);
    dst[1] = make_float4(wh[4],  wh[5],  wh[6],  wh[7]);
    dst[2] = make_float4(wh[8],  wh[9],  wh[10], wh[11]);
    dst[3] = make_float4(wh[12], wh[13], wh[14], wh[15]);
    g_ej[base] = e2;
}

// ============================================================
// K2: per (b,h): M = max ej, p = exp(ej-M), write p AND
//     Q^T hi/lo bf16 directly (coalesced 8B stores along j)
// ============================================================
__global__ __launch_bounds__(256) void gat_pexp() {
    __shared__ float wmax[8];
    int tid = threadIdx.x, lane = tid & 31, warp = tid >> 5;
    int bh = blockIdx.x, b = bh >> 3, h = bh & 7;

    float4 e = ((const float4*)(g_ej + (size_t)bh * NN))[tid];
    float m = fmaxf(fmaxf(e.x, e.y), fmaxf(e.z, e.w));
    #pragma unroll
    for (int off = 16; off; off >>= 1)
        m = fmaxf(m, __shfl_xor_sync(0xffffffffu, m, off));
    if (lane == 0) wmax[warp] = m;
    __syncthreads();
    float M = wmax[0];
    #pragma unroll
    for (int w = 1; w < 8; w++) M = fmaxf(M, wmax[w]);

    float4 p = make_float4(__expf(e.x - M), __expf(e.y - M),
                           __expf(e.z - M), __expf(e.w - M));
    ((float4*)(g_p + (size_t)bh * NN))[tid] = p;
    const float pv[4] = {p.x, p.y, p.z, p.w};

    #pragma unroll
    for (int half = 0; half < 2; half++) {
        float qa[4][8];
        #pragma unroll
        for (int k = 0; k < 4; k++) {
            const float4* w = (const float4*)&g_Wh[((size_t)bh * NN + tid * 4 + k) * DD];
            float4 w0 = w[half * 2 + 0], w1 = w[half * 2 + 1];
            qa[k][0] = w0.x * pv[k]; qa[k][1] = w0.y * pv[k];
            qa[k][2] = w0.z * pv[k]; qa[k][3] = w0.w * pv[k];
            qa[k][4] = w1.x * pv[k]; qa[k][5] = w1.y * pv[k];
            qa[k][6] = w1.z * pv[k]; qa[k][7] = w1.w * pv[k];
        }
        #pragma unroll
        for (int cc = 0; cc < 8; cc++) {
            int c = half * 8 + cc;
            unsigned w0 = cvt2bf(qa[0][cc], qa[1][cc]);
            unsigned w1 = cvt2bf(qa[2][cc], qa[3][cc]);
            size_t row = (size_t)b * 128 + h * 16 + c;
            *(uint2*)&g_Qth[row * NN + tid * 4] = make_uint2(w0, w1);
            float h0 = __uint_as_float(w0 << 16);
            float h1 = __uint_as_float(w0 & 0xFFFF0000u);
            float h2 = __uint_as_float(w1 << 16);
            float h3 = __uint_as_float(w1 & 0xFFFF0000u);
            unsigned l0 = cvt2bf(qa[0][cc] - h0, qa[1][cc] - h1);
            unsigned l1 = cvt2bf(qa[2][cc] - h2, qa[3][cc] - h3);
            *(uint2*)&g_Qtl[row * NN + tid * 4] = make_uint2(l0, l1);
        }
    }
}

// ============================================================
// K3: S[i][h] = adj_row . p_h  -> invS;  adj -> bf16 copy
// ============================================================
__global__ __launch_bounds__(256) void gat_sadj(const int* __restrict__ adj) {
    int tid = threadIdx.x, l = tid & 31, h = tid >> 5;
    int b = blockIdx.x >> 5;
    int i0 = (blockIdx.x & 31) * 32;

    float4 pk[8];
    const float4* pp = (const float4*)(g_p + ((size_t)b * HH + h) * NN);
    #pragma unroll
    for (int k = 0; k < 8; k++) pk[k] = pp[k * 32 + l];

    for (int r = 0; r < 32; r++) {
        int row = i0 + r;
        const int4* arow = (const int4*)(adj + ((size_t)b * NN + row) * NN);
        bool conv = ((r & 7) == (h & 7));   // warp h converts rows r%8==h
        float s = 0.f;
        #pragma unroll
        for (int k = 0; k < 8; k++) {
            int4 av = arow[k * 32 + l];
            float m0 = (float)av.x, m1 = (float)av.y;
            float m2 = (float)av.z, m3 = (float)av.w;
            s += m0 * pk[k].x + m1 * pk[k].y + m2 * pk[k].z + m3 * pk[k].w;
            if (conv) {
                unsigned w0 = (av.x ? 0x3F80u : 0u) | (av.y ? 0x3F800000u : 0u);
                unsigned w1 = (av.z ? 0x3F80u : 0u) | (av.w ? 0x3F800000u : 0u);
                *(uint2*)&g_adjb[((size_t)b * NN + row) * NN + (k * 32 + l) * 4] =
                    make_uint2(w0, w1);
            }
        }
        #pragma unroll
        for (int off = 16; off; off >>= 1)
            s += __shfl_xor_sync(0xffffffffu, s, off);
        if (l == 0)
            g_invS[((size_t)b * NN + row) * 8 + h] = (s > 0.f) ? (1.f / s) : (1.f / NN);
    }
}

// ============================================================
// K4: mma.sync GEMM  H[64 x 128] = adj_bf16 @ (Qhi + Qlo)
//     epilogue: hprime = relu(H * invS)
// grid 128 (b * 16 tiles of 64 rows), 256 threads (8 warps 2x4)
// ============================================================
__global__ __launch_bounds__(256) void gat_mma(float* __restrict__ hprime) {
    __shared__ __align__(16) unsigned char sA [64  * 128];  //  8KB
    __shared__ __align__(16) unsigned char sBh[128 * 128];  // 16KB
    __shared__ __align__(16) unsigned char sBl[128 * 128];  // 16KB
    __shared__ float sS[64 * 8];                            //  2KB

    int tid = threadIdx.x, wid = tid >> 5, lane = tid & 31;
    int b  = blockIdx.x >> 4;
    int i0 = (blockIdx.x & 15) * 64;

    for (int k = tid; k < 512; k += 256)
        sS[k] = g_invS[((size_t)b * NN + i0) * 8 + k];

    int warp_m = wid & 1, warp_n = wid >> 1;  // 2 x 4
    int mbase = warp_m * 32;
    int g = lane >> 2, q = lane & 3;

    float acc[2][4][4];
    #pragma unroll
    for (int mt = 0; mt < 2; mt++)
        #pragma unroll
        for (int nt = 0; nt < 4; nt++)
            #pragma unroll
            for (int k = 0; k < 4; k++) acc[mt][nt][k] = 0.f;

    uint32_t baseA  = smem_u32(sA);
    uint32_t baseBh = smem_u32(sBh);
    uint32_t baseBl = smem_u32(sBl);

    const uint4* gA = (const uint4*)(g_adjb + ((size_t)(b * NN + i0)) * NN);
    const uint4* gB = (const uint4*)(g_Qth + (size_t)b * 128 * NN);
    const uint4* gL = (const uint4*)(g_Qtl + (size_t)b * 128 * NN);

    for (int ch = 0; ch < 16; ch++) {
        int jc8 = ch * 8;   // 64 bf16 = 8 uint4 per row-chunk
        __syncthreads();
        // stage A (64 rows x 128B)
        #pragma unroll
        for (int it = 0; it < 2; it++) {
            int idx = it * 256 + tid;           // 0..511
            int r = idx >> 3, u = idx & 7;
            *(uint4*)(sA + r * 128 + ((u ^ (r & 7)) * 16)) =
                gA[(size_t)r * 128 + jc8 + u];
        }
        // stage Bh, Bl (128 rows x 128B each)
        #pragma unroll
        for (int it = 0; it < 4; it++) {
            int idx = it * 256 + tid;           // 0..1023
            int r = idx >> 3, u = idx & 7;
            int off = r * 128 + ((u ^ (r & 7)) * 16);
            *(uint4*)(sBh + off) = gB[(size_t)r * 128 + jc8 + u];
            *(uint4*)(sBl + off) = gL[(size_t)r * 128 + jc8 + u];
        }
        __syncthreads();

        #pragma unroll
        for (int k16 = 0; k16 < 4; k16++) {
            uint32_t a[2][4];
            #pragma unroll
            for (int mt = 0; mt < 2; mt++) {
                int rr = mbase + mt * 16 + (lane & 15);
                int kc = k16 * 2 + (lane >> 4);
                ldmx4(a[mt][0], a[mt][1], a[mt][2], a[mt][3],
                      baseA + rr * 128 + ((kc ^ (rr & 7)) * 16));
            }
            #pragma unroll
            for (int half = 0; half < 2; half++) {
                uint32_t bb = half ? baseBl : baseBh;
                #pragma unroll
                for (int np = 0; np < 2; np++) {
                    int nr = warp_n * 32 + np * 16 + (lane & 7) + ((lane >> 4) << 3);
                    int kc = k16 * 2 + ((lane >> 3) & 1);
                    uint32_t m0, m1, m2, m3;
                    ldmx4(m0, m1, m2, m3, bb + nr * 128 + ((kc ^ (nr & 7)) * 16));
                    #pragma unroll
                    for (int mt = 0; mt < 2; mt++) {
                        mma16816(acc[mt][np * 2],     a[mt], m0, m1);
                        mma16816(acc[mt][np * 2 + 1], a[mt], m2, m3);
                    }
                }
            }
        }
    }
    __syncthreads();

    // ---- epilogue ----
    #pragma unroll
    for (int mt = 0; mt < 2; mt++) {
        #pragma unroll
        for (int nt = 0; nt < 4; nt++) {
            int np = nt >> 1;
            int h = warp_n * 2 + np;
            int col = warp_n * 32 + np * 16 + (nt & 1) * 8 + 2 * q;
            int r0 = mbase + mt * 16 + g;
            int r1 = r0 + 8;
            float v0 = sS[r0 * 8 + h], v1 = sS[r1 * 8 + h];
            float2 o0 = make_float2(fmaxf(acc[mt][nt][0] * v0, 0.f),
                                    fmaxf(acc[mt][nt][1] * v0, 0.f));
            float2 o1 = make_float2(fmaxf(acc[mt][nt][2] * v1, 0.f),
                                    fmaxf(acc[mt][nt][3] * v1, 0.f));
            *(float2*)&hprime[((size_t)b * NN + i0 + r0) * 128 + col] = o0;
            *(float2*)&hprime[((size_t)b * NN + i0 + r1) * 128 + col] = o1;
        }
    }
}

// ============================================================
// K5: alpha[b,h,i,j] = adj_bf16[b,i,j] * p_h[j] * invS[i][h]
// ============================================================
__global__ __launch_bounds__(256) void gat_alpha(float* __restrict__ alpha) {
    __shared__ float sInv[32 * 8];
    int tid = threadIdx.x;
    int b = blockIdx.x >> 5;
    int i0 = (blockIdx.x & 31) * 32;

    float4 P[8];
    #pragma unroll
    for (int h = 0; h < 8; h++)
        P[h] = ((const float4*)(g_p + ((size_t)b * HH + h) * NN))[tid];

    sInv[tid] = g_invS[((size_t)b * NN + i0) * 8 + tid];
    __syncthreads();

    const unsigned short* abase = g_adjb + ((size_t)b * NN + i0) * NN + tid * 4;
    uint2 mv = *(const uint2*)abase;
    for (int r = 0; r < 32; r++) {
        uint2 nxt = make_uint2(0, 0);
        if (r < 31) nxt = *(const uint2*)(abase + (size_t)(r + 1) * NN);
        float m0 = __uint_as_float(mv.x << 16);
        float m1 = __uint_as_float(mv.x & 0xFFFF0000u);
        float m2 = __uint_as_float(mv.y << 16);
        float m3 = __uint_as_float(mv.y & 0xFFFF0000u);
        int i = i0 + r;
        #pragma unroll
        for (int h = 0; h < 8; h++) {
            float inv = sInv[r * 8 + h];
            float4 o = make_float4(m0 * (P[h].x * inv), m1 * (P[h].y * inv),
                                   m2 * (P[h].z * inv), m3 * (P[h].w * inv));
            __stwt((float4*)&alpha[(((size_t)(b * HH + h)) * NN + i) * NN + tid * 4], o);
        }
        mv = nxt;
    }
}

// ============================================================
extern "C" void kernel_launch(void* const* d_in, const int* in_sizes, int n_in,
                              void* d_out, int out_size) {
    const float* x   = (const float*)d_in[0];   // (8,1024,25)
    const int*   adj = (const int*)  d_in[1];   // (8,1024,1024)
    const float* W   = (const float*)d_in[2];   // (8,25,16)
    const float* a   = (const float*)d_in[3];   // (8,32,1)

    float* out    = (float*)d_out;
    float* hprime = out;                                 // (8,1024,128)
    float* alpha  = out + (size_t)BB * NN * HH * DD;     // (8,8,1024,1024)

    gat_prep<<<BB * (NN / 32), 256>>>(x, W, a);
    gat_pexp<<<BB * HH, 256>>>();
    gat_sadj<<<BB * 32, 256>>>(adj);
    gat_mma<<<BB * 16, 256>>>(hprime);
    gat_alpha<<<BB * 32, 256>>>(alpha);
}

// round 16
// speedup vs baseline: 1.3457x; 1.1216x over previous
#include <cuda_runtime.h>
#include <cuda_bf16.h>
#include <cstdint>

#define BB 8
#define NN 1024
#define FIN 25
#define HH 8
#define DD 16

// -------- device scratch --------
__device__ float g_Wh[(size_t)BB*HH*NN*DD];         // (b,h,n,d) 4MB
__device__ float g_ej[(size_t)BB*HH*NN];
__device__ float g_p [(size_t)BB*HH*NN];            // (b,h,n)
__device__ float g_invS[(size_t)BB*NN*HH];          // (b,n,h)
__device__ unsigned short g_adjb[(size_t)BB*NN*NN]; // adj as bf16, 16MB
__device__ unsigned short g_Qth[(size_t)BB*128*NN]; // Q^T hi bf16 (b,c,j) 2MB
__device__ unsigned short g_Qtl[(size_t)BB*128*NN]; // Q^T lo bf16 2MB

// ---- helpers ----
__device__ __forceinline__ uint32_t smem_u32(const void* p) {
    uint32_t a;
    asm("{ .reg .u64 t; cvta.to.shared.u64 t, %1; cvt.u32.u64 %0, t; }" : "=r"(a) : "l"(p));
    return a;
}
__device__ __forceinline__ unsigned cvt2bf(float lo, float hi) {
    unsigned r;
    asm("cvt.rn.bf16x2.f32 %0, %1, %2;" : "=r"(r) : "f"(hi), "f"(lo));
    return r;
}
__device__ __forceinline__ void ldmx4(uint32_t& r0, uint32_t& r1, uint32_t& r2,
                                      uint32_t& r3, uint32_t addr) {
    asm volatile("ldmatrix.sync.aligned.m8n8.x4.shared.b16 {%0,%1,%2,%3}, [%4];"
                 : "=r"(r0), "=r"(r1), "=r"(r2), "=r"(r3) : "r"(addr));
}
__device__ __forceinline__ void mma16816(float* d, const uint32_t* a,
                                         uint32_t b0, uint32_t b1) {
    asm volatile("mma.sync.aligned.m16n8k16.row.col.f32.bf16.bf16.f32 "
                 "{%0,%1,%2,%3}, {%4,%5,%6,%7}, {%8,%9}, {%0,%1,%2,%3};"
                 : "+f"(d[0]), "+f"(d[1]), "+f"(d[2]), "+f"(d[3])
                 : "r"(a[0]), "r"(a[1]), "r"(a[2]), "r"(a[3]), "r"(b0), "r"(b1));
}
__device__ __forceinline__ void cp16(uint32_t dst, const void* src) {
    asm volatile("cp.async.cg.shared.global [%0], [%1], 16;" :: "r"(dst), "l"(src));
}
__device__ __forceinline__ void cp_commit() {
    asm volatile("cp.async.commit_group;");
}
__device__ __forceinline__ void cp_wait1() {
    asm volatile("cp.async.wait_group 1;");
}
__device__ __forceinline__ void cp_wait0() {
    asm volatile("cp.async.wait_group 0;");
}

// ============================================================
// K1: Wh = x@W per head, ej = Wh . a_dst
// ============================================================
__global__ __launch_bounds__(256) void gat_prep(const float* __restrict__ x,
                                                const float* __restrict__ W,
                                                const float* __restrict__ a) {
    __shared__ float s_W[HH * 401];
    __shared__ float s_x[32 * FIN];
    __shared__ float s_a[HH * 32];

    int tid = threadIdx.x;
    int b  = blockIdx.x >> 5;
    int n0 = (blockIdx.x & 31) * 32;

    for (int idx = tid; idx < HH * 400; idx += 256) {
        int h = idx / 400, rem = idx - h * 400;
        s_W[h * 401 + rem] = W[idx];
    }
    s_a[tid] = a[tid];
    for (int idx = tid; idx < 32 * FIN; idx += 256)
        s_x[idx] = x[((size_t)b * NN + n0) * FIN + idx];
    __syncthreads();

    int nl = tid >> 3;
    int h  = tid & 7;

    float wh[DD];
    #pragma unroll
    for (int d = 0; d < DD; d++) wh[d] = 0.f;

    const float* wbase = &s_W[h * 401];
    const float* xr    = &s_x[nl * FIN];
    #pragma unroll
    for (int f = 0; f < FIN; f++) {
        float xv = xr[f];
        #pragma unroll
        for (int d = 0; d < DD; d++) wh[d] += xv * wbase[f * 16 + d];
    }

    float e2 = 0.f;
    #pragma unroll
    for (int d = 0; d < DD; d++) e2 += wh[d] * s_a[h * 32 + 16 + d];

    size_t base = ((size_t)(b * HH + h) * NN + n0 + nl);
    float4* dst = (float4*)&g_Wh[base * DD];
    dst[0] = make_float4(wh[0],  wh[1],  wh[2],  wh[3]);
    dst[1] = make_float4(wh[4],  wh[5],  wh[6],  wh[7]);
    dst[2] = make_float4(wh[8],  wh[9],  wh[10], wh[11]);
    dst[3] = make_float4(wh[12], wh[13], wh[14], wh[15]);
    g_ej[base] = e2;
}

// ============================================================
// K2: per (b,h): M = max ej, p = exp(ej-M), write p AND
//     Q^T hi/lo bf16 directly (coalesced 8B stores along j)
// ============================================================
__global__ __launch_bounds__(256) void gat_pexp() {
    __shared__ float wmax[8];
    int tid = threadIdx.x, lane = tid & 31, warp = tid >> 5;
    int bh = blockIdx.x, b = bh >> 3, h = bh & 7;

    float4 e = ((const float4*)(g_ej + (size_t)bh * NN))[tid];
    float m = fmaxf(fmaxf(e.x, e.y), fmaxf(e.z, e.w));
    #pragma unroll
    for (int off = 16; off; off >>= 1)
        m = fmaxf(m, __shfl_xor_sync(0xffffffffu, m, off));
    if (lane == 0) wmax[warp] = m;
    __syncthreads();
    float M = wmax[0];
    #pragma unroll
    for (int w = 1; w < 8; w++) M = fmaxf(M, wmax[w]);

    float4 p = make_float4(__expf(e.x - M), __expf(e.y - M),
                           __expf(e.z - M), __expf(e.w - M));
    ((float4*)(g_p + (size_t)bh * NN))[tid] = p;
    const float pv[4] = {p.x, p.y, p.z, p.w};

    #pragma unroll
    for (int half = 0; half < 2; half++) {
        float qa[4][8];
        #pragma unroll
        for (int k = 0; k < 4; k++) {
            const float4* w = (const float4*)&g_Wh[((size_t)bh * NN + tid * 4 + k) * DD];
            float4 w0 = w[half * 2 + 0], w1 = w[half * 2 + 1];
            qa[k][0] = w0.x * pv[k]; qa[k][1] = w0.y * pv[k];
            qa[k][2] = w0.z * pv[k]; qa[k][3] = w0.w * pv[k];
            qa[k][4] = w1.x * pv[k]; qa[k][5] = w1.y * pv[k];
            qa[k][6] = w1.z * pv[k]; qa[k][7] = w1.w * pv[k];
        }
        #pragma unroll
        for (int cc = 0; cc < 8; cc++) {
            int c = half * 8 + cc;
            unsigned w0 = cvt2bf(qa[0][cc], qa[1][cc]);
            unsigned w1 = cvt2bf(qa[2][cc], qa[3][cc]);
            size_t row = (size_t)b * 128 + h * 16 + c;
            *(uint2*)&g_Qth[row * NN + tid * 4] = make_uint2(w0, w1);
            float h0 = __uint_as_float(w0 << 16);
            float h1 = __uint_as_float(w0 & 0xFFFF0000u);
            float h2 = __uint_as_float(w1 << 16);
            float h3 = __uint_as_float(w1 & 0xFFFF0000u);
            unsigned l0 = cvt2bf(qa[0][cc] - h0, qa[1][cc] - h1);
            unsigned l1 = cvt2bf(qa[2][cc] - h2, qa[3][cc] - h3);
            *(uint2*)&g_Qtl[row * NN + tid * 4] = make_uint2(l0, l1);
        }
    }
}

// ============================================================
// K3: S[i][h] = adj_row . p_h  -> invS;  adj -> bf16 copy
// ============================================================
__global__ __launch_bounds__(256) void gat_sadj(const int* __restrict__ adj) {
    int tid = threadIdx.x, l = tid & 31, h = tid >> 5;
    int b = blockIdx.x >> 5;
    int i0 = (blockIdx.x & 31) * 32;

    float4 pk[8];
    const float4* pp = (const float4*)(g_p + ((size_t)b * HH + h) * NN);
    #pragma unroll
    for (int k = 0; k < 8; k++) pk[k] = pp[k * 32 + l];

    for (int r = 0; r < 32; r++) {
        int row = i0 + r;
        const int4* arow = (const int4*)(adj + ((size_t)b * NN + row) * NN);
        bool conv = ((r & 7) == (h & 7));   // warp h converts rows r%8==h
        float s = 0.f;
        #pragma unroll
        for (int k = 0; k < 8; k++) {
            int4 av = arow[k * 32 + l];
            float m0 = (float)av.x, m1 = (float)av.y;
            float m2 = (float)av.z, m3 = (float)av.w;
            s += m0 * pk[k].x + m1 * pk[k].y + m2 * pk[k].z + m3 * pk[k].w;
            if (conv) {
                unsigned w0 = (av.x ? 0x3F80u : 0u) | (av.y ? 0x3F800000u : 0u);
                unsigned w1 = (av.z ? 0x3F80u : 0u) | (av.w ? 0x3F800000u : 0u);
                *(uint2*)&g_adjb[((size_t)b * NN + row) * NN + (k * 32 + l) * 4] =
                    make_uint2(w0, w1);
            }
        }
        #pragma unroll
        for (int off = 16; off; off >>= 1)
            s += __shfl_xor_sync(0xffffffffu, s, off);
        if (l == 0)
            g_invS[((size_t)b * NN + row) * 8 + h] = (s > 0.f) ? (1.f / s) : (1.f / NN);
    }
}

// ============================================================
// K4: mma.sync GEMM  H[64 x 128] = adj_bf16 @ (Qhi + Qlo)
//     cp.async double-buffered staging; epilogue relu(H*invS)
// grid 128 (b * 16 tiles of 64 rows), 256 threads (8 warps 2x4)
// dyn smem: sA[2][8K] | sBh[2][16K] | sBl[2][16K] | sS[2K] = 84KB
// ============================================================
#define OFF_A  0
#define OFF_BH 16384
#define OFF_BL 49152
#define OFF_S  81920
#define K4_SMEM (81920 + 2048)

extern __shared__ unsigned char k4smem[];

__global__ __launch_bounds__(256) void gat_mma(float* __restrict__ hprime) {
    int tid = threadIdx.x, wid = tid >> 5, lane = tid & 31;
    int b  = blockIdx.x >> 4;
    int i0 = (blockIdx.x & 15) * 64;

    float* sS = (float*)(k4smem + OFF_S);
    for (int k = tid; k < 512; k += 256)
        sS[k] = g_invS[((size_t)b * NN + i0) * 8 + k];

    int warp_m = wid & 1, warp_n = wid >> 1;  // 2 x 4
    int mbase = warp_m * 32;
    int g = lane >> 2, q = lane & 3;

    float acc[2][4][4];
    #pragma unroll
    for (int mt = 0; mt < 2; mt++)
        #pragma unroll
        for (int nt = 0; nt < 4; nt++)
            #pragma unroll
            for (int k = 0; k < 4; k++) acc[mt][nt][k] = 0.f;

    uint32_t base = smem_u32(k4smem);

    const uint4* gA = (const uint4*)(g_adjb + ((size_t)(b * NN + i0)) * NN);
    const uint4* gB = (const uint4*)(g_Qth + (size_t)b * 128 * NN);
    const uint4* gL = (const uint4*)(g_Qtl + (size_t)b * 128 * NN);

    // ---- async stage of one chunk into buffer `buf` ----
    auto stage = [&](int buf, int ch) {
        int jc8 = ch * 8;
        uint32_t dA  = base + OFF_A  + buf * 8192;
        uint32_t dBh = base + OFF_BH + buf * 16384;
        uint32_t dBl = base + OFF_BL + buf * 16384;
        #pragma unroll
        for (int it = 0; it < 2; it++) {
            int idx = it * 256 + tid;           // 0..511
            int r = idx >> 3, u = idx & 7;
            cp16(dA + r * 128 + ((u ^ (r & 7)) * 16), &gA[(size_t)r * 128 + jc8 + u]);
        }
        #pragma unroll
        for (int it = 0; it < 4; it++) {
            int idx = it * 256 + tid;           // 0..1023
            int r = idx >> 3, u = idx & 7;
            int off = r * 128 + ((u ^ (r & 7)) * 16);
            cp16(dBh + off, &gB[(size_t)r * 128 + jc8 + u]);
            cp16(dBl + off, &gL[(size_t)r * 128 + jc8 + u]);
        }
        cp_commit();
    };

    stage(0, 0);

    for (int ch = 0; ch < 16; ch++) {
        int buf = ch & 1;
        if (ch + 1 < 16) {
            stage(buf ^ 1, ch + 1);
            cp_wait1();
        } else {
            cp_wait0();
        }
        __syncthreads();

        uint32_t baseA  = base + OFF_A  + buf * 8192;
        uint32_t baseBh = base + OFF_BH + buf * 16384;
        uint32_t baseBl = base + OFF_BL + buf * 16384;

        #pragma unroll
        for (int k16 = 0; k16 < 4; k16++) {
            uint32_t a[2][4];
            #pragma unroll
            for (int mt = 0; mt < 2; mt++) {
                int rr = mbase + mt * 16 + (lane & 15);
                int kc = k16 * 2 + (lane >> 4);
                ldmx4(a[mt][0], a[mt][1], a[mt][2], a[mt][3],
                      baseA + rr * 128 + ((kc ^ (rr & 7)) * 16));
            }
            #pragma unroll
            for (int half = 0; half < 2; half++) {
                uint32_t bb = half ? baseBl : baseBh;
                #pragma unroll
                for (int np = 0; np < 2; np++) {
                    int nr = warp_n * 32 + np * 16 + (lane & 7) + ((lane >> 4) << 3);
                    int kc = k16 * 2 + ((lane >> 3) & 1);
                    uint32_t m0, m1, m2, m3;
                    ldmx4(m0, m1, m2, m3, bb + nr * 128 + ((kc ^ (nr & 7)) * 16));
                    #pragma unroll
                    for (int mt = 0; mt < 2; mt++) {
                        mma16816(acc[mt][np * 2],     a[mt], m0, m1);
                        mma16816(acc[mt][np * 2 + 1], a[mt], m2, m3);
                    }
                }
            }
        }
        __syncthreads();   // compute(buf) done before stage overwrites it next iter
    }

    // ---- epilogue ----
    #pragma unroll
    for (int mt = 0; mt < 2; mt++) {
        #pragma unroll
        for (int nt = 0; nt < 4; nt++) {
            int np = nt >> 1;
            int h = warp_n * 2 + np;
            int col = warp_n * 32 + np * 16 + (nt & 1) * 8 + 2 * q;
            int r0 = mbase + mt * 16 + g;
            int r1 = r0 + 8;
            float v0 = sS[r0 * 8 + h], v1 = sS[r1 * 8 + h];
            float2 o0 = make_float2(fmaxf(acc[mt][nt][0] * v0, 0.f),
                                    fmaxf(acc[mt][nt][1] * v0, 0.f));
            float2 o1 = make_float2(fmaxf(acc[mt][nt][2] * v1, 0.f),
                                    fmaxf(acc[mt][nt][3] * v1, 0.f));
            *(float2*)&hprime[((size_t)b * NN + i0 + r0) * 128 + col] = o0;
            *(float2*)&hprime[((size_t)b * NN + i0 + r1) * 128 + col] = o1;
        }
    }
}

// ============================================================
// K5: alpha[b,h,i,j] = adj_bf16[b,i,j] * p_h[j] * invS[i][h]
// ============================================================
__global__ __launch_bounds__(256) void gat_alpha(float* __restrict__ alpha) {
    __shared__ float sInv[32 * 8];
    int tid = threadIdx.x;
    int b = blockIdx.x >> 5;
    int i0 = (blockIdx.x & 31) * 32;

    float4 P[8];
    #pragma unroll
    for (int h = 0; h < 8; h++)
        P[h] = ((const float4*)(g_p + ((size_t)b * HH + h) * NN))[tid];

    sInv[tid] = g_invS[((size_t)b * NN + i0) * 8 + tid];
    __syncthreads();

    const unsigned short* abase = g_adjb + ((size_t)b * NN + i0) * NN + tid * 4;
    uint2 mv = *(const uint2*)abase;
    for (int r = 0; r < 32; r++) {
        uint2 nxt = make_uint2(0, 0);
        if (r < 31) nxt = *(const uint2*)(abase + (size_t)(r + 1) * NN);
        float m0 = __uint_as_float(mv.x << 16);
        float m1 = __uint_as_float(mv.x & 0xFFFF0000u);
        float m2 = __uint_as_float(mv.y << 16);
        float m3 = __uint_as_float(mv.y & 0xFFFF0000u);
        int i = i0 + r;
        #pragma unroll
        for (int h = 0; h < 8; h++) {
            float inv = sInv[r * 8 + h];
            float4 o = make_float4(m0 * (P[h].x * inv), m1 * (P[h].y * inv),
                                   m2 * (P[h].z * inv), m3 * (P[h].w * inv));
            __stwt((float4*)&alpha[(((size_t)(b * HH + h)) * NN + i) * NN + tid * 4], o);
        }
        mv = nxt;
    }
}

// ============================================================
extern "C" void kernel_launch(void* const* d_in, const int* in_sizes, int n_in,
                              void* d_out, int out_size) {
    const float* x   = (const float*)d_in[0];   // (8,1024,25)
    const int*   adj = (const int*)  d_in[1];   // (8,1024,1024)
    const float* W   = (const float*)d_in[2];   // (8,25,16)
    const float* a   = (const float*)d_in[3];   // (8,32,1)

    float* out    = (float*)d_out;
    float* hprime = out;                                 // (8,1024,128)
    float* alpha  = out + (size_t)BB * NN * HH * DD;     // (8,8,1024,1024)

    cudaFuncSetAttribute(gat_mma, cudaFuncAttributeMaxDynamicSharedMemorySize, K4_SMEM);

    gat_prep<<<BB * (NN / 32), 256>>>(x, W, a);
    gat_pexp<<<BB * HH, 256>>>();
    gat_sadj<<<BB * 32, 256>>>(adj);
    gat_mma<<<BB * 16, 256, K4_SMEM>>>(hprime);
    gat_alpha<<<BB * 32, 256>>>(alpha);
}